// round 16
// baseline (speedup 1.0000x reference)
#include <cuda_runtime.h>
#include <cuda_fp16.h>
#include <cstdint>

// Problem dims (fixed by the dataset)
constexpr int Bb = 4, Cc = 512, Tt = 16, Hh = 32, Ww = 32;
constexpr int Ss = Tt * Hh * Ww;     // 16384 tokens per batch
constexpr int Nn = Bb * Ss;          // 65536 tokens total

// Scratch (static __device__ arrays: allocation-guard safe)
__device__ __half g_X[(size_t)Nn * Cc];
__device__ __half g_QKV[(size_t)Nn * 4608];
__device__ __half g_O[(size_t)Nn * 1536];
__device__ __half g_Wqkv[4608 * 512];
__device__ __half g_Wo[512 * 1536];
__device__ float  g_bias[512];

__device__ __forceinline__ void cp_async16(uint32_t dst, const void* src) {
    asm volatile("cp.async.cg.shared.global [%0],[%1],16;" :: "r"(dst), "l"(src));
}
__device__ __forceinline__ uint32_t smem_u32(const void* p) {
    uint32_t a;
    asm("{ .reg .u64 t; cvta.to.shared.u64 t, %1; cvt.u32.u64 %0, t; }"
        : "=r"(a) : "l"(p));
    return a;
}
__device__ __forceinline__ void ldsm_x4(uint32_t addr, uint32_t* r) {
    asm volatile("ldmatrix.sync.aligned.m8n8.x4.shared.b16 {%0,%1,%2,%3},[%4];"
                 : "=r"(r[0]), "=r"(r[1]), "=r"(r[2]), "=r"(r[3]) : "r"(addr));
}
__device__ __forceinline__ void ldsm_x4_t(uint32_t addr, uint32_t* r) {
    asm volatile("ldmatrix.sync.aligned.m8n8.x4.trans.shared.b16 {%0,%1,%2,%3},[%4];"
                 : "=r"(r[0]), "=r"(r[1]), "=r"(r[2]), "=r"(r[3]) : "r"(addr));
}
__device__ __forceinline__ void mma16816(float* c, const uint32_t* a,
                                         uint32_t b0, uint32_t b1) {
    asm volatile(
        "mma.sync.aligned.m16n8k16.row.col.f32.f16.f16.f32 "
        "{%0,%1,%2,%3},{%4,%5,%6,%7},{%8,%9},{%0,%1,%2,%3};"
        : "+f"(c[0]), "+f"(c[1]), "+f"(c[2]), "+f"(c[3])
        : "r"(a[0]), "r"(a[1]), "r"(a[2]), "r"(a[3]), "r"(b0), "r"(b1));
}
// streaming (evict-first) stores
__device__ __forceinline__ void stcs_u32(void* p, uint32_t v) {
    asm volatile("st.global.cs.b32 [%0], %1;" :: "l"(p), "r"(v) : "memory");
}
__device__ __forceinline__ void stcs_f2(void* p, float2 v) {
    asm volatile("st.global.cs.v2.f32 [%0], {%1,%2};" :: "l"(p), "f"(v.x), "f"(v.y)
                 : "memory");
}

// ---------------------------------------------------------------------------
// Weight prep (single merged kernel: Wqkv + Wo + bias)
// ---------------------------------------------------------------------------
__global__ void prep_all_k(const float* __restrict__ wq0, const float* __restrict__ wk0,
                           const float* __restrict__ wv0, const float* __restrict__ wq1,
                           const float* __restrict__ wk1, const float* __restrict__ wv1,
                           const float* __restrict__ wq2, const float* __restrict__ wk2,
                           const float* __restrict__ wv2, const float* __restrict__ wo0,
                           const float* __restrict__ wo1, const float* __restrict__ wo2,
                           const float* __restrict__ b0, const float* __restrict__ b1,
                           const float* __restrict__ b2) {
    int i = blockIdx.x * blockDim.x + threadIdx.x;
    if (i < 512) g_bias[i] = b0[i] + b1[i] + b2[i];
    if (i < 3 * 786432) {                       // Wqkv: 2.36M elements
        int ax = i / 786432, r = i % 786432;
        const float* srcs[9] = {wq0, wk0, wv0, wq1, wk1, wv1, wq2, wk2, wv2};
        g_Wqkv[i] = __float2half_rn(srcs[ax * 3 + (r >> 18)][r & 262143]);
    }
    int j = i - 3 * 786432;
    if (j >= 0 && j < 3 * 262144) {             // Wo: 0.79M elements
        int ax = j >> 18, r = j & 262143;
        const float* w = (ax == 0) ? wo0 : (ax == 1 ? wo1 : wo2);
        int c = r >> 9, col = r & 511;
        g_Wo[c * 1536 + ax * 512 + col] = __float2half_rn(w[r]);
    }
}

// ---------------------------------------------------------------------------
// Transpose in: x (B, C, S) fp32 -> g_X (N, C) fp16 (vectorized)
// ---------------------------------------------------------------------------
__global__ void transpose_in_k(const float* __restrict__ x) {
    __shared__ float tile[64][33];
    int s0 = blockIdx.x * 32, c0 = blockIdx.y * 64, b = blockIdx.z;
    int tx = threadIdx.x, ty = threadIdx.y;  // block (32, 8)
    const float* src = x + (size_t)b * Cc * Ss;
    #pragma unroll
    for (int i = 0; i < 8; i++)
        tile[ty + i * 8][tx] = src[(size_t)(c0 + ty + i * 8) * Ss + s0 + tx];
    __syncthreads();
    #pragma unroll
    for (int j = 0; j < 4; j++) {
        int s = ty * 4 + j;
        __half2 v = __floats2half2_rn(tile[2 * tx][s], tile[2 * tx + 1][s]);
        *reinterpret_cast<__half2*>(g_X + (size_t)(b * Ss + s0 + s) * Cc + c0 + 2 * tx) = v;
    }
}

// ---------------------------------------------------------------------------
// QKV GEMM, BK=128 variant: C[Nn,4608] = X[Nn,512] * Wqkv^T
// CTA 128x96, warp 64x48, 2-stage double buffer with 256B smem rows,
// ONLY 4 barrier boundaries (vs 8 at BK=64). 112KB smem -> 2 CTAs/SM.
// ---------------------------------------------------------------------------
constexpr int QK_STAGE = 57344;              // A 32KB + B 24KB
constexpr int QK_DSMEM = 2 * QK_STAGE + 1024;

__global__ void __launch_bounds__(128, 2)
gemm_qkv_k(const __half* __restrict__ A, const __half* __restrict__ Bw,
           __half* __restrict__ C) {
    extern __shared__ char dyn[];
    uint32_t base = (smem_u32(dyn) + 1023) & ~1023u;

    const int tid = threadIdx.x;
    const int lane = tid & 31, warp = tid >> 5;
    const int wm = warp & 1, wn = warp >> 1;     // 2 (M) x 2 (N)
    const int bM = blockIdx.y * 128, bN = blockIdx.x * 96;

    const __half* Ab = A + (size_t)bM * 512;
    const __half* Bt = Bw + (size_t)bN * 512;

    float acc[4][6][4];
    #pragma unroll
    for (int i = 0; i < 4; i++)
        #pragma unroll
        for (int j = 0; j < 6; j++)
            #pragma unroll
            for (int q = 0; q < 4; q++) acc[i][j][q] = 0.f;

    // Stage: A 128 rows x 256B (16 chunks), B 96 rows x 256B.
    auto loadStage = [&](int ld) {
        uint32_t ab = base + (uint32_t)(ld & 1) * QK_STAGE;
        uint32_t bb = ab + 32768;
        int k0 = ld * 128;
        #pragma unroll
        for (int i = 0; i < 16; i++) {           // A: 2048 chunks / 128 thr
            int idx = tid + i * 128;
            int row = idx >> 4, c = idx & 15;
            uint32_t sw = (uint32_t)row * 256 + (uint32_t)((c ^ (row & 7)) << 4);
            cp_async16(ab + sw, Ab + (size_t)row * 512 + k0 + c * 8);
        }
        #pragma unroll
        for (int i = 0; i < 12; i++) {           // B: 1536 chunks / 128 thr
            int idx = tid + i * 128;
            int row = idx >> 4, c = idx & 15;
            uint32_t sw = (uint32_t)row * 256 + (uint32_t)((c ^ (row & 7)) << 4);
            cp_async16(bb + sw, Bt + (size_t)row * 512 + k0 + c * 8);
        }
        asm volatile("cp.async.commit_group;");
    };

    loadStage(0);

    #pragma unroll 1
    for (int kt = 0; kt < 4; kt++) {
        asm volatile("cp.async.wait_group 0;");
        __syncthreads();                 // stage kt visible; compute(kt-1) done
        if (kt + 1 < 4) loadStage(kt + 1);

        uint32_t aBase = base + (uint32_t)(kt & 1) * QK_STAGE;
        uint32_t bBase = aBase + 32768;

        #pragma unroll
        for (int ks = 0; ks < 8; ks++) {         // 8 k16 steps per BK=128
            uint32_t af[4][4];
            #pragma unroll
            for (int mt = 0; mt < 4; mt++) {
                int row = wm * 64 + mt * 16 + (lane & 15);
                int kc = ks * 2 + (lane >> 4);
                ldsm_x4(aBase + (uint32_t)row * 256 + (uint32_t)((kc ^ (row & 7)) << 4),
                        af[mt]);
            }
            uint32_t bf[3][4];
            #pragma unroll
            for (int np = 0; np < 3; np++) {
                int row = wn * 48 + np * 16 + (lane & 7) + ((lane >> 4) << 3);
                int kc = ks * 2 + ((lane >> 3) & 1);
                ldsm_x4(bBase + (uint32_t)row * 256 + (uint32_t)((kc ^ (row & 7)) << 4),
                        bf[np]);
            }
            #pragma unroll
            for (int mt = 0; mt < 4; mt++)
                #pragma unroll
                for (int np = 0; np < 3; np++) {
                    mma16816(acc[mt][np * 2], af[mt], bf[np][0], bf[np][1]);
                    mma16816(acc[mt][np * 2 + 1], af[mt], bf[np][2], bf[np][3]);
                }
        }
    }

    #pragma unroll
    for (int mt = 0; mt < 4; mt++) {
        #pragma unroll
        for (int nt = 0; nt < 6; nt++) {
            int row = bM + wm * 64 + mt * 16 + (lane >> 2);
            int col = bN + wn * 48 + nt * 8 + (lane & 3) * 2;
            size_t o0 = (size_t)row * 4608 + col;
            size_t o1 = (size_t)(row + 8) * 4608 + col;
            __half2 v0 = __floats2half2_rn(acc[mt][nt][0], acc[mt][nt][1]);
            __half2 v1 = __floats2half2_rn(acc[mt][nt][2], acc[mt][nt][3]);
            stcs_u32(C + o0, *reinterpret_cast<uint32_t*>(&v0));
            stcs_u32(C + o1, *reinterpret_cast<uint32_t*>(&v1));
        }
    }
}

// ---------------------------------------------------------------------------
// Out-proj GEMM (BK=64, 3-stage, 97KB, 2 CTAs/SM), ALL batches via gridDim.z.
// ---------------------------------------------------------------------------
constexpr int STAGES = 3;
constexpr int STAGE_BYTES = 32768;
constexpr int GEMM_DSMEM = STAGES * STAGE_BYTES + 1024;

__global__ void __launch_bounds__(128, 2)
gemm_out_k(const __half* __restrict__ A, const __half* __restrict__ Bw,
           float* __restrict__ C, const float* __restrict__ bias) {
    extern __shared__ char dyn[];
    uint32_t base = (smem_u32(dyn) + 1023) & ~1023u;

    const int tid = threadIdx.x;
    const int lane = tid & 31, warp = tid >> 5;
    const int wm = warp & 1, wn = warp >> 1;
    const int bM = blockIdx.x * 128;
    const int bN = blockIdx.y * 128;
    constexpr int K = 1536, KT = 24;

    const __half* Ab = A + (size_t)bM * K;
    const __half* Bt = Bw + (size_t)blockIdx.z * Ss * K + (size_t)bN * K;
    float* Cb = C + (size_t)blockIdx.z * Cc * Ss;

    float acc[4][8][4];
    #pragma unroll
    for (int i = 0; i < 4; i++)
        #pragma unroll
        for (int j = 0; j < 8; j++)
            #pragma unroll
            for (int q = 0; q < 4; q++) acc[i][j][q] = 0.f;

    auto loadStage = [&](int ld) {
        uint32_t ab = base + (uint32_t)(ld % STAGES) * STAGE_BYTES;
        uint32_t bb = ab + 16384;
        int k0 = ld * 64;
        #pragma unroll
        for (int i = 0; i < 8; i++) {
            int idx = tid + i * 128;
            int row = idx >> 3, c = idx & 7;
            uint32_t sw = (uint32_t)row * 128 + (uint32_t)((c ^ (row & 7)) << 4);
            cp_async16(ab + sw, Ab + (size_t)row * K + k0 + c * 8);
            cp_async16(bb + sw, Bt + (size_t)row * K + k0 + c * 8);
        }
        asm volatile("cp.async.commit_group;");
    };

    loadStage(0);
    loadStage(1);

    #pragma unroll 1
    for (int kt = 0; kt < KT; kt++) {
        asm volatile("cp.async.wait_group 1;");
        __syncthreads();
        if (kt + 2 < KT) {
            loadStage(kt + 2);
        } else {
            asm volatile("cp.async.commit_group;");
        }

        uint32_t aBase = base + (uint32_t)(kt % STAGES) * STAGE_BYTES;
        uint32_t bBase = aBase + 16384;

        #pragma unroll
        for (int ks = 0; ks < 4; ks++) {
            uint32_t af[4][4];
            #pragma unroll
            for (int mt = 0; mt < 4; mt++) {
                int row = wm * 64 + mt * 16 + (lane & 15);
                int kc = ks * 2 + (lane >> 4);
                ldsm_x4(aBase + (uint32_t)row * 128 + (uint32_t)((kc ^ (row & 7)) << 4),
                        af[mt]);
            }
            uint32_t bf[4][4];
            #pragma unroll
            for (int np = 0; np < 4; np++) {
                int row = wn * 64 + np * 16 + (lane & 7) + ((lane >> 4) << 3);
                int kc = ks * 2 + ((lane >> 3) & 1);
                ldsm_x4(bBase + (uint32_t)row * 128 + (uint32_t)((kc ^ (row & 7)) << 4),
                        bf[np]);
            }
            #pragma unroll
            for (int mt = 0; mt < 4; mt++)
                #pragma unroll
                for (int np = 0; np < 4; np++) {
                    mma16816(acc[mt][np * 2], af[mt], bf[np][0], bf[np][1]);
                    mma16816(acc[mt][np * 2 + 1], af[mt], bf[np][2], bf[np][3]);
                }
        }
    }

    #pragma unroll
    for (int mt = 0; mt < 4; mt++) {
        #pragma unroll
        for (int nt = 0; nt < 8; nt++) {
            int row = bM + wm * 64 + mt * 16 + (lane >> 2);
            int col = bN + wn * 64 + nt * 8 + (lane & 3) * 2;
            float v0 = acc[mt][nt][0] + bias[row];
            float v1 = acc[mt][nt][1] + bias[row];
            float v2 = acc[mt][nt][2] + bias[row + 8];
            float v3 = acc[mt][nt][3] + bias[row + 8];
            stcs_f2(Cb + (size_t)row * Ss + col, make_float2(v0, v1));
            stcs_f2(Cb + (size_t)(row + 8) * Ss + col, make_float2(v2, v3));
        }
    }
}

// ---------------------------------------------------------------------------
// Merged tensor-core axial attention (one launch for all axes/batches).
// ---------------------------------------------------------------------------
template <int L>
__device__ __forceinline__ void attn_body(int axis, int hp, int n0, int st,
                                          uint32_t base, int tid) {
    const int lane = tid & 31, wp = tid >> 5;

    #pragma unroll
    for (int m = 0; m < 3; m++) {
        #pragma unroll
        for (int i = 0; i < (L * 32) / 128; i++) {
            int idx = tid + i * 128;
            int row = idx >> 5, c = idx & 31;
            const __half* src = g_QKV + (size_t)(n0 + row * st) * 4608 +
                                axis * 1536 + m * 512 + hp * 256 + c * 8;
            uint32_t dst = base + (uint32_t)(m * L * 512) + (uint32_t)row * 512 +
                           (uint32_t)((c ^ (row & 7)) << 4);
            cp_async16(dst, src);
        }
    }
    asm volatile("cp.async.commit_group;");
    asm volatile("cp.async.wait_group 0;");
    __syncthreads();

    const uint32_t smQ = base, smK = base + L * 512, smV = base + 2 * L * 512;
    constexpr int MT = L / 16, NT = L / 8, NP = NT / 2;
    const int cb = wp * 8;

    float P[MT][NT][4];
    #pragma unroll
    for (int mt = 0; mt < MT; mt++)
        #pragma unroll
        for (int nt = 0; nt < NT; nt++)
            #pragma unroll
            for (int q = 0; q < 4; q++) P[mt][nt][q] = 0.f;

    #pragma unroll
    for (int kt = 0; kt < 4; kt++) {
        uint32_t aQ[MT][4];
        #pragma unroll
        for (int mt = 0; mt < MT; mt++) {
            int row = mt * 16 + (lane & 15);
            int c = cb + kt * 2 + (lane >> 4);
            ldsm_x4(smQ + (uint32_t)row * 512 + (uint32_t)((c ^ (row & 7)) << 4), aQ[mt]);
        }
        #pragma unroll
        for (int np = 0; np < NP; np++) {
            uint32_t bK[4];
            int row = np * 16 + (lane & 7) + ((lane >> 4) << 3);
            int c = cb + kt * 2 + ((lane >> 3) & 1);
            ldsm_x4(smK + (uint32_t)row * 512 + (uint32_t)((c ^ (row & 7)) << 4), bK);
            #pragma unroll
            for (int mt = 0; mt < MT; mt++) {
                mma16816(P[mt][np * 2], aQ[mt], bK[0], bK[1]);
                mma16816(P[mt][np * 2 + 1], aQ[mt], bK[2], bK[3]);
            }
        }
    }

    uint32_t aP[MT][NP][4];
    #pragma unroll
    for (int mt = 0; mt < MT; mt++) {
        float mx0 = -1e30f, mx1 = -1e30f;
        #pragma unroll
        for (int nt = 0; nt < NT; nt++) {
            mx0 = fmaxf(mx0, fmaxf(P[mt][nt][0], P[mt][nt][1]));
            mx1 = fmaxf(mx1, fmaxf(P[mt][nt][2], P[mt][nt][3]));
        }
        mx0 = fmaxf(mx0, __shfl_xor_sync(0xFFFFFFFFu, mx0, 1));
        mx0 = fmaxf(mx0, __shfl_xor_sync(0xFFFFFFFFu, mx0, 2));
        mx1 = fmaxf(mx1, __shfl_xor_sync(0xFFFFFFFFu, mx1, 1));
        mx1 = fmaxf(mx1, __shfl_xor_sync(0xFFFFFFFFu, mx1, 2));
        float s0 = 0.f, s1 = 0.f;
        #pragma unroll
        for (int nt = 0; nt < NT; nt++) {
            float e0 = __expf((P[mt][nt][0] - mx0) * 0.125f);
            float e1 = __expf((P[mt][nt][1] - mx0) * 0.125f);
            float e2 = __expf((P[mt][nt][2] - mx1) * 0.125f);
            float e3 = __expf((P[mt][nt][3] - mx1) * 0.125f);
            P[mt][nt][0] = e0; P[mt][nt][1] = e1;
            P[mt][nt][2] = e2; P[mt][nt][3] = e3;
            s0 += e0 + e1; s1 += e2 + e3;
        }
        s0 += __shfl_xor_sync(0xFFFFFFFFu, s0, 1);
        s0 += __shfl_xor_sync(0xFFFFFFFFu, s0, 2);
        s1 += __shfl_xor_sync(0xFFFFFFFFu, s1, 1);
        s1 += __shfl_xor_sync(0xFFFFFFFFu, s1, 2);
        float inv0 = 1.f / s0, inv1 = 1.f / s1;
        #pragma unroll
        for (int np = 0; np < NP; np++) {
            __half2 p0 = __floats2half2_rn(P[mt][2 * np][0] * inv0, P[mt][2 * np][1] * inv0);
            __half2 p1 = __floats2half2_rn(P[mt][2 * np][2] * inv1, P[mt][2 * np][3] * inv1);
            __half2 p2 = __floats2half2_rn(P[mt][2 * np + 1][0] * inv0, P[mt][2 * np + 1][1] * inv0);
            __half2 p3 = __floats2half2_rn(P[mt][2 * np + 1][2] * inv1, P[mt][2 * np + 1][3] * inv1);
            aP[mt][np][0] = *reinterpret_cast<uint32_t*>(&p0);
            aP[mt][np][1] = *reinterpret_cast<uint32_t*>(&p1);
            aP[mt][np][2] = *reinterpret_cast<uint32_t*>(&p2);
            aP[mt][np][3] = *reinterpret_cast<uint32_t*>(&p3);
        }
    }

    float O[MT][8][4];
    #pragma unroll
    for (int mt = 0; mt < MT; mt++)
        #pragma unroll
        for (int nt = 0; nt < 8; nt++)
            #pragma unroll
            for (int q = 0; q < 4; q++) O[mt][nt][q] = 0.f;

    #pragma unroll
    for (int kt = 0; kt < NP; kt++) {
        #pragma unroll
        for (int vp = 0; vp < 4; vp++) {
            uint32_t bV[4];
            int krow = kt * 16 + (lane & 7) + (((lane >> 3) & 1) << 3);
            int c = cb + vp * 2 + (lane >> 4);
            ldsm_x4_t(smV + (uint32_t)krow * 512 + (uint32_t)((c ^ (krow & 7)) << 4), bV);
            #pragma unroll
            for (int mt = 0; mt < MT; mt++) {
                mma16816(O[mt][vp * 2], aP[mt][kt], bV[0], bV[1]);
                mma16816(O[mt][vp * 2 + 1], aP[mt][kt], bV[2], bV[3]);
            }
        }
    }

    const int ocol0 = axis * 512 + (hp * 4 + wp) * 64;
    #pragma unroll
    for (int mt = 0; mt < MT; mt++) {
        int r = mt * 16 + (lane >> 2);
        size_t rowOffA = (size_t)(n0 + r * st) * 1536 + ocol0;
        size_t rowOffB = (size_t)(n0 + (r + 8) * st) * 1536 + ocol0;
        #pragma unroll
        for (int nt = 0; nt < 8; nt++) {
            int col = nt * 8 + (lane & 3) * 2;
            *reinterpret_cast<__half2*>(g_O + rowOffA + col) =
                __floats2half2_rn(O[mt][nt][0], O[mt][nt][1]);
            *reinterpret_cast<__half2*>(g_O + rowOffB + col) =
                __floats2half2_rn(O[mt][nt][2], O[mt][nt][3]);
        }
    }
}

__global__ void __launch_bounds__(128)
attn_all_k() {
    extern __shared__ __align__(128) char sm[];
    const uint32_t base = smem_u32(sm);
    const int tid = threadIdx.x;
    const int id = blockIdx.x;

    if (id < 8192) {                         // axes w (0..4095) and h (4096..8191)
        int axis = id >> 12;
        int r = id & 4095;
        int b = r >> 10;
        int g = r & 1023;
        int hp = g & 1, grp = g >> 1;
        int n0, st;
        if (axis == 0) { n0 = b * Ss + grp * 32;                        st = 1;  }
        else           { n0 = b * Ss + (grp >> 5) * 1024 + (grp & 31);  st = 32; }
        attn_body<32>(axis, hp, n0, st, base, tid);
    } else {                                 // axis t (8192..16383)
        int r = id - 8192;
        int b = r >> 11;
        int g = r & 2047;
        int hp = g & 1, grp = g >> 1;
        attn_body<16>(2, hp, b * Ss + grp, 1024, base, tid);
    }
}

// ---------------------------------------------------------------------------
// Launch: pure serial on the default stream. 5 kernels.
// ---------------------------------------------------------------------------
extern "C" void kernel_launch(void* const* d_in, const int* in_sizes, int n_in,
                              void* d_out, int out_size) {
    (void)in_sizes; (void)n_in; (void)out_size;
    const float* x = (const float*)d_in[0];
    const float* wq[3] = {(const float*)d_in[1],  (const float*)d_in[6],  (const float*)d_in[11]};
    const float* wk[3] = {(const float*)d_in[2],  (const float*)d_in[7],  (const float*)d_in[12]};
    const float* wv[3] = {(const float*)d_in[3],  (const float*)d_in[8],  (const float*)d_in[13]};
    const float* wo[3] = {(const float*)d_in[4],  (const float*)d_in[9],  (const float*)d_in[14]};
    const float* bo[3] = {(const float*)d_in[5],  (const float*)d_in[10], (const float*)d_in[15]};
    float* out = (float*)d_out;

    void *pX, *pQKV, *pO, *pWqkv, *pWo, *pBias;
    cudaGetSymbolAddress(&pX, g_X);
    cudaGetSymbolAddress(&pQKV, g_QKV);
    cudaGetSymbolAddress(&pO, g_O);
    cudaGetSymbolAddress(&pWqkv, g_Wqkv);
    cudaGetSymbolAddress(&pWo, g_Wo);
    cudaGetSymbolAddress(&pBias, g_bias);

    cudaFuncSetAttribute(gemm_qkv_k,
                         cudaFuncAttributeMaxDynamicSharedMemorySize, QK_DSMEM);
    cudaFuncSetAttribute(gemm_out_k,
                         cudaFuncAttributeMaxDynamicSharedMemorySize, GEMM_DSMEM);
    cudaFuncSetAttribute(attn_all_k,
                         cudaFuncAttributeMaxDynamicSharedMemorySize, 3 * 32 * 512);

    // 0: all weight prep (merged)
    prep_all_k<<<(3 * 786432 + 3 * 262144 + 255) / 256, 256>>>(
        wq[0], wk[0], wv[0], wq[1], wk[1], wv[1], wq[2], wk[2], wv[2],
        wo[0], wo[1], wo[2], bo[0], bo[1], bo[2]);
    // 1: input transpose
    transpose_in_k<<<dim3(Ss / 32, Cc / 64, Bb), dim3(32, 8)>>>(x);

    // 2: fused QKV projection (BK=128, 4 pipeline boundaries)
    gemm_qkv_k<<<dim3(4608 / 96, Nn / 128), 128, QK_DSMEM>>>(
        (const __half*)pX, (const __half*)pWqkv, (__half*)pQKV);

    // 3: all axial attention in one launch
    attn_all_k<<<16384, 128, 3 * 32 * 512>>>();

    // 4: output projection, all batches
    gemm_out_k<<<dim3(4, Ss / 128, Bb), 128, GEMM_DSMEM>>>(
        (const __half*)pWo, (const __half*)pO, out, (const float*)pBias);
}

// round 17
// speedup vs baseline: 1.0451x; 1.0451x over previous
#include <cuda_runtime.h>
#include <cuda_fp16.h>
#include <cstdint>

// Problem dims (fixed by the dataset)
constexpr int Bb = 4, Cc = 512, Tt = 16, Hh = 32, Ww = 32;
constexpr int Ss = Tt * Hh * Ww;     // 16384 tokens per batch
constexpr int Nn = Bb * Ss;          // 65536 tokens total

// Scratch (static __device__ arrays: allocation-guard safe)
__device__ __half g_X[(size_t)Nn * Cc];
__device__ __half g_QKV[(size_t)Nn * 4608];
__device__ __half g_O[(size_t)Nn * 1536];
__device__ __half g_Wqkv[4608 * 512];
__device__ __half g_Wo[512 * 1536];
__device__ float  g_bias[512];

__device__ __forceinline__ void cp_async16(uint32_t dst, const void* src) {
    asm volatile("cp.async.cg.shared.global [%0],[%1],16;" :: "r"(dst), "l"(src));
}
__device__ __forceinline__ uint32_t smem_u32(const void* p) {
    uint32_t a;
    asm("{ .reg .u64 t; cvta.to.shared.u64 t, %1; cvt.u32.u64 %0, t; }"
        : "=r"(a) : "l"(p));
    return a;
}
__device__ __forceinline__ void ldsm_x4(uint32_t addr, uint32_t* r) {
    asm volatile("ldmatrix.sync.aligned.m8n8.x4.shared.b16 {%0,%1,%2,%3},[%4];"
                 : "=r"(r[0]), "=r"(r[1]), "=r"(r[2]), "=r"(r[3]) : "r"(addr));
}
__device__ __forceinline__ void ldsm_x4_t(uint32_t addr, uint32_t* r) {
    asm volatile("ldmatrix.sync.aligned.m8n8.x4.trans.shared.b16 {%0,%1,%2,%3},[%4];"
                 : "=r"(r[0]), "=r"(r[1]), "=r"(r[2]), "=r"(r[3]) : "r"(addr));
}
__device__ __forceinline__ void mma16816(float* c, const uint32_t* a,
                                         uint32_t b0, uint32_t b1) {
    asm volatile(
        "mma.sync.aligned.m16n8k16.row.col.f32.f16.f16.f32 "
        "{%0,%1,%2,%3},{%4,%5,%6,%7},{%8,%9},{%0,%1,%2,%3};"
        : "+f"(c[0]), "+f"(c[1]), "+f"(c[2]), "+f"(c[3])
        : "r"(a[0]), "r"(a[1]), "r"(a[2]), "r"(a[3]), "r"(b0), "r"(b1));
}
// streaming (evict-first) stores
__device__ __forceinline__ void stcs_u32(void* p, uint32_t v) {
    asm volatile("st.global.cs.b32 [%0], %1;" :: "l"(p), "r"(v) : "memory");
}
__device__ __forceinline__ void stcs_f2(void* p, float2 v) {
    asm volatile("st.global.cs.v2.f32 [%0], {%1,%2};" :: "l"(p), "f"(v.x), "f"(v.y)
                 : "memory");
}

// ---------------------------------------------------------------------------
// Weight prep (single merged kernel: Wqkv + Wo + bias)
// ---------------------------------------------------------------------------
__global__ void prep_all_k(const float* __restrict__ wq0, const float* __restrict__ wk0,
                           const float* __restrict__ wv0, const float* __restrict__ wq1,
                           const float* __restrict__ wk1, const float* __restrict__ wv1,
                           const float* __restrict__ wq2, const float* __restrict__ wk2,
                           const float* __restrict__ wv2, const float* __restrict__ wo0,
                           const float* __restrict__ wo1, const float* __restrict__ wo2,
                           const float* __restrict__ b0, const float* __restrict__ b1,
                           const float* __restrict__ b2) {
    int i = blockIdx.x * blockDim.x + threadIdx.x;
    if (i < 512) g_bias[i] = b0[i] + b1[i] + b2[i];
    if (i < 3 * 786432) {                       // Wqkv: 2.36M elements
        int ax = i / 786432, r = i % 786432;
        const float* srcs[9] = {wq0, wk0, wv0, wq1, wk1, wv1, wq2, wk2, wv2};
        g_Wqkv[i] = __float2half_rn(srcs[ax * 3 + (r >> 18)][r & 262143]);
    }
    int j = i - 3 * 786432;
    if (j >= 0 && j < 3 * 262144) {             // Wo: 0.79M elements
        int ax = j >> 18, r = j & 262143;
        const float* w = (ax == 0) ? wo0 : (ax == 1 ? wo1 : wo2);
        int c = r >> 9, col = r & 511;
        g_Wo[c * 1536 + ax * 512 + col] = __float2half_rn(w[r]);
    }
}

// ---------------------------------------------------------------------------
// Transpose in: x (B, C, S) fp32 -> g_X (N, C) fp16 (vectorized)
// ---------------------------------------------------------------------------
__global__ void transpose_in_k(const float* __restrict__ x) {
    __shared__ float tile[64][33];
    int s0 = blockIdx.x * 32, c0 = blockIdx.y * 64, b = blockIdx.z;
    int tx = threadIdx.x, ty = threadIdx.y;  // block (32, 8)
    const float* src = x + (size_t)b * Cc * Ss;
    #pragma unroll
    for (int i = 0; i < 8; i++)
        tile[ty + i * 8][tx] = src[(size_t)(c0 + ty + i * 8) * Ss + s0 + tx];
    __syncthreads();
    #pragma unroll
    for (int j = 0; j < 4; j++) {
        int s = ty * 4 + j;
        __half2 v = __floats2half2_rn(tile[2 * tx][s], tile[2 * tx + 1][s]);
        *reinterpret_cast<__half2*>(g_X + (size_t)(b * Ss + s0 + s) * Cc + c0 + 2 * tx) = v;
    }
}

// ---------------------------------------------------------------------------
// QKV GEMM (champion config: BK=64, 2-stage, 3 CTAs/SM):
// C[Nn,4608] = X[Nn,512] * Wqkv^T. CTA 128x96, 4 warps (2x2), warp 64x48.
// ---------------------------------------------------------------------------
constexpr int QK_STAGE = 28672;              // A 16KB + B 12KB
constexpr int QK_DSMEM = 2 * QK_STAGE + 1024;

__global__ void __launch_bounds__(128, 3)
gemm_qkv_k(const __half* __restrict__ A, const __half* __restrict__ Bw,
           __half* __restrict__ C) {
    extern __shared__ char dyn[];
    uint32_t base = (smem_u32(dyn) + 1023) & ~1023u;

    const int tid = threadIdx.x;
    const int lane = tid & 31, warp = tid >> 5;
    const int wm = warp & 1, wn = warp >> 1;     // 2 (M) x 2 (N)
    const int bM = blockIdx.y * 128, bN = blockIdx.x * 96;

    const __half* Ab = A + (size_t)bM * 512;
    const __half* Bt = Bw + (size_t)bN * 512;

    float acc[4][6][4];
    #pragma unroll
    for (int i = 0; i < 4; i++)
        #pragma unroll
        for (int j = 0; j < 6; j++)
            #pragma unroll
            for (int q = 0; q < 4; q++) acc[i][j][q] = 0.f;

    auto loadStage = [&](int ld) {
        uint32_t ab = base + (uint32_t)(ld & 1) * QK_STAGE;
        uint32_t bb = ab + 16384;
        int k0 = ld * 64;
        #pragma unroll
        for (int i = 0; i < 8; i++) {
            int idx = tid + i * 128;
            int row = idx >> 3, c = idx & 7;
            uint32_t sw = (uint32_t)row * 128 + (uint32_t)((c ^ (row & 7)) << 4);
            cp_async16(ab + sw, Ab + (size_t)row * 512 + k0 + c * 8);
        }
        #pragma unroll
        for (int i = 0; i < 6; i++) {
            int idx = tid + i * 128;
            int row = idx >> 3, c = idx & 7;
            uint32_t sw = (uint32_t)row * 128 + (uint32_t)((c ^ (row & 7)) << 4);
            cp_async16(bb + sw, Bt + (size_t)row * 512 + k0 + c * 8);
        }
        asm volatile("cp.async.commit_group;");
    };

    loadStage(0);

    #pragma unroll 1
    for (int kt = 0; kt < 8; kt++) {
        asm volatile("cp.async.wait_group 0;");
        __syncthreads();                 // stage kt visible; compute(kt-1) done
        if (kt + 1 < 8) loadStage(kt + 1);

        uint32_t aBase = base + (uint32_t)(kt & 1) * QK_STAGE;
        uint32_t bBase = aBase + 16384;

        #pragma unroll
        for (int ks = 0; ks < 4; ks++) {
            uint32_t af[4][4];
            #pragma unroll
            for (int mt = 0; mt < 4; mt++) {
                int row = wm * 64 + mt * 16 + (lane & 15);
                int kc = ks * 2 + (lane >> 4);
                ldsm_x4(aBase + (uint32_t)row * 128 + (uint32_t)((kc ^ (row & 7)) << 4),
                        af[mt]);
            }
            uint32_t bf[3][4];
            #pragma unroll
            for (int np = 0; np < 3; np++) {
                int row = wn * 48 + np * 16 + (lane & 7) + ((lane >> 4) << 3);
                int kc = ks * 2 + ((lane >> 3) & 1);
                ldsm_x4(bBase + (uint32_t)row * 128 + (uint32_t)((kc ^ (row & 7)) << 4),
                        bf[np]);
            }
            #pragma unroll
            for (int mt = 0; mt < 4; mt++)
                #pragma unroll
                for (int np = 0; np < 3; np++) {
                    mma16816(acc[mt][np * 2], af[mt], bf[np][0], bf[np][1]);
                    mma16816(acc[mt][np * 2 + 1], af[mt], bf[np][2], bf[np][3]);
                }
        }
    }

    #pragma unroll
    for (int mt = 0; mt < 4; mt++) {
        #pragma unroll
        for (int nt = 0; nt < 6; nt++) {
            int row = bM + wm * 64 + mt * 16 + (lane >> 2);
            int col = bN + wn * 48 + nt * 8 + (lane & 3) * 2;
            size_t o0 = (size_t)row * 4608 + col;
            size_t o1 = (size_t)(row + 8) * 4608 + col;
            __half2 v0 = __floats2half2_rn(acc[mt][nt][0], acc[mt][nt][1]);
            __half2 v1 = __floats2half2_rn(acc[mt][nt][2], acc[mt][nt][3]);
            stcs_u32(C + o0, *reinterpret_cast<uint32_t*>(&v0));
            stcs_u32(C + o1, *reinterpret_cast<uint32_t*>(&v1));
        }
    }
}

// ---------------------------------------------------------------------------
// Out-proj GEMM (BK=64, 3-stage, 97KB, 2 CTAs/SM), ALL batches via gridDim.z.
// blockIdx.x indexes the 4 Wo blocks (fastest) -> O tiles read once from HBM.
// ---------------------------------------------------------------------------
constexpr int STAGES = 3;
constexpr int STAGE_BYTES = 32768;
constexpr int GEMM_DSMEM = STAGES * STAGE_BYTES + 1024;

__global__ void __launch_bounds__(128, 2)
gemm_out_k(const __half* __restrict__ A, const __half* __restrict__ Bw,
           float* __restrict__ C, const float* __restrict__ bias) {
    extern __shared__ char dyn[];
    uint32_t base = (smem_u32(dyn) + 1023) & ~1023u;

    const int tid = threadIdx.x;
    const int lane = tid & 31, warp = tid >> 5;
    const int wm = warp & 1, wn = warp >> 1;
    const int bM = blockIdx.x * 128;
    const int bN = blockIdx.y * 128;
    constexpr int K = 1536, KT = 24;

    const __half* Ab = A + (size_t)bM * K;
    const __half* Bt = Bw + (size_t)blockIdx.z * Ss * K + (size_t)bN * K;
    float* Cb = C + (size_t)blockIdx.z * Cc * Ss;

    float acc[4][8][4];
    #pragma unroll
    for (int i = 0; i < 4; i++)
        #pragma unroll
        for (int j = 0; j < 8; j++)
            #pragma unroll
            for (int q = 0; q < 4; q++) acc[i][j][q] = 0.f;

    auto loadStage = [&](int ld) {
        uint32_t ab = base + (uint32_t)(ld % STAGES) * STAGE_BYTES;
        uint32_t bb = ab + 16384;
        int k0 = ld * 64;
        #pragma unroll
        for (int i = 0; i < 8; i++) {
            int idx = tid + i * 128;
            int row = idx >> 3, c = idx & 7;
            uint32_t sw = (uint32_t)row * 128 + (uint32_t)((c ^ (row & 7)) << 4);
            cp_async16(ab + sw, Ab + (size_t)row * K + k0 + c * 8);
            cp_async16(bb + sw, Bt + (size_t)row * K + k0 + c * 8);
        }
        asm volatile("cp.async.commit_group;");
    };

    loadStage(0);
    loadStage(1);

    #pragma unroll 1
    for (int kt = 0; kt < KT; kt++) {
        asm volatile("cp.async.wait_group 1;");
        __syncthreads();
        if (kt + 2 < KT) {
            loadStage(kt + 2);
        } else {
            asm volatile("cp.async.commit_group;");
        }

        uint32_t aBase = base + (uint32_t)(kt % STAGES) * STAGE_BYTES;
        uint32_t bBase = aBase + 16384;

        #pragma unroll
        for (int ks = 0; ks < 4; ks++) {
            uint32_t af[4][4];
            #pragma unroll
            for (int mt = 0; mt < 4; mt++) {
                int row = wm * 64 + mt * 16 + (lane & 15);
                int kc = ks * 2 + (lane >> 4);
                ldsm_x4(aBase + (uint32_t)row * 128 + (uint32_t)((kc ^ (row & 7)) << 4),
                        af[mt]);
            }
            uint32_t bf[4][4];
            #pragma unroll
            for (int np = 0; np < 4; np++) {
                int row = wn * 64 + np * 16 + (lane & 7) + ((lane >> 4) << 3);
                int kc = ks * 2 + ((lane >> 3) & 1);
                ldsm_x4(bBase + (uint32_t)row * 128 + (uint32_t)((kc ^ (row & 7)) << 4),
                        bf[np]);
            }
            #pragma unroll
            for (int mt = 0; mt < 4; mt++)
                #pragma unroll
                for (int np = 0; np < 4; np++) {
                    mma16816(acc[mt][np * 2], af[mt], bf[np][0], bf[np][1]);
                    mma16816(acc[mt][np * 2 + 1], af[mt], bf[np][2], bf[np][3]);
                }
        }
    }

    #pragma unroll
    for (int mt = 0; mt < 4; mt++) {
        #pragma unroll
        for (int nt = 0; nt < 8; nt++) {
            int row = bM + wm * 64 + mt * 16 + (lane >> 2);
            int col = bN + wn * 64 + nt * 8 + (lane & 3) * 2;
            float v0 = acc[mt][nt][0] + bias[row];
            float v1 = acc[mt][nt][1] + bias[row];
            float v2 = acc[mt][nt][2] + bias[row + 8];
            float v3 = acc[mt][nt][3] + bias[row + 8];
            stcs_f2(Cb + (size_t)row * Ss + col, make_float2(v0, v1));
            stcs_f2(Cb + (size_t)(row + 8) * Ss + col, make_float2(v2, v3));
        }
    }
}

// ---------------------------------------------------------------------------
// Merged tensor-core axial attention (one launch for all axes/batches).
// DRAM-roofline bound at ~122us (measured 80.4% of HBM spec).
// ---------------------------------------------------------------------------
template <int L>
__device__ __forceinline__ void attn_body(int axis, int hp, int n0, int st,
                                          uint32_t base, int tid) {
    const int lane = tid & 31, wp = tid >> 5;

    #pragma unroll
    for (int m = 0; m < 3; m++) {
        #pragma unroll
        for (int i = 0; i < (L * 32) / 128; i++) {
            int idx = tid + i * 128;
            int row = idx >> 5, c = idx & 31;
            const __half* src = g_QKV + (size_t)(n0 + row * st) * 4608 +
                                axis * 1536 + m * 512 + hp * 256 + c * 8;
            uint32_t dst = base + (uint32_t)(m * L * 512) + (uint32_t)row * 512 +
                           (uint32_t)((c ^ (row & 7)) << 4);
            cp_async16(dst, src);
        }
    }
    asm volatile("cp.async.commit_group;");
    asm volatile("cp.async.wait_group 0;");
    __syncthreads();

    const uint32_t smQ = base, smK = base + L * 512, smV = base + 2 * L * 512;
    constexpr int MT = L / 16, NT = L / 8, NP = NT / 2;
    const int cb = wp * 8;

    float P[MT][NT][4];
    #pragma unroll
    for (int mt = 0; mt < MT; mt++)
        #pragma unroll
        for (int nt = 0; nt < NT; nt++)
            #pragma unroll
            for (int q = 0; q < 4; q++) P[mt][nt][q] = 0.f;

    #pragma unroll
    for (int kt = 0; kt < 4; kt++) {
        uint32_t aQ[MT][4];
        #pragma unroll
        for (int mt = 0; mt < MT; mt++) {
            int row = mt * 16 + (lane & 15);
            int c = cb + kt * 2 + (lane >> 4);
            ldsm_x4(smQ + (uint32_t)row * 512 + (uint32_t)((c ^ (row & 7)) << 4), aQ[mt]);
        }
        #pragma unroll
        for (int np = 0; np < NP; np++) {
            uint32_t bK[4];
            int row = np * 16 + (lane & 7) + ((lane >> 4) << 3);
            int c = cb + kt * 2 + ((lane >> 3) & 1);
            ldsm_x4(smK + (uint32_t)row * 512 + (uint32_t)((c ^ (row & 7)) << 4), bK);
            #pragma unroll
            for (int mt = 0; mt < MT; mt++) {
                mma16816(P[mt][np * 2], aQ[mt], bK[0], bK[1]);
                mma16816(P[mt][np * 2 + 1], aQ[mt], bK[2], bK[3]);
            }
        }
    }

    uint32_t aP[MT][NP][4];
    #pragma unroll
    for (int mt = 0; mt < MT; mt++) {
        float mx0 = -1e30f, mx1 = -1e30f;
        #pragma unroll
        for (int nt = 0; nt < NT; nt++) {
            mx0 = fmaxf(mx0, fmaxf(P[mt][nt][0], P[mt][nt][1]));
            mx1 = fmaxf(mx1, fmaxf(P[mt][nt][2], P[mt][nt][3]));
        }
        mx0 = fmaxf(mx0, __shfl_xor_sync(0xFFFFFFFFu, mx0, 1));
        mx0 = fmaxf(mx0, __shfl_xor_sync(0xFFFFFFFFu, mx0, 2));
        mx1 = fmaxf(mx1, __shfl_xor_sync(0xFFFFFFFFu, mx1, 1));
        mx1 = fmaxf(mx1, __shfl_xor_sync(0xFFFFFFFFu, mx1, 2));
        float s0 = 0.f, s1 = 0.f;
        #pragma unroll
        for (int nt = 0; nt < NT; nt++) {
            float e0 = __expf((P[mt][nt][0] - mx0) * 0.125f);
            float e1 = __expf((P[mt][nt][1] - mx0) * 0.125f);
            float e2 = __expf((P[mt][nt][2] - mx1) * 0.125f);
            float e3 = __expf((P[mt][nt][3] - mx1) * 0.125f);
            P[mt][nt][0] = e0; P[mt][nt][1] = e1;
            P[mt][nt][2] = e2; P[mt][nt][3] = e3;
            s0 += e0 + e1; s1 += e2 + e3;
        }
        s0 += __shfl_xor_sync(0xFFFFFFFFu, s0, 1);
        s0 += __shfl_xor_sync(0xFFFFFFFFu, s0, 2);
        s1 += __shfl_xor_sync(0xFFFFFFFFu, s1, 1);
        s1 += __shfl_xor_sync(0xFFFFFFFFu, s1, 2);
        float inv0 = 1.f / s0, inv1 = 1.f / s1;
        #pragma unroll
        for (int np = 0; np < NP; np++) {
            __half2 p0 = __floats2half2_rn(P[mt][2 * np][0] * inv0, P[mt][2 * np][1] * inv0);
            __half2 p1 = __floats2half2_rn(P[mt][2 * np][2] * inv1, P[mt][2 * np][3] * inv1);
            __half2 p2 = __floats2half2_rn(P[mt][2 * np + 1][0] * inv0, P[mt][2 * np + 1][1] * inv0);
            __half2 p3 = __floats2half2_rn(P[mt][2 * np + 1][2] * inv1, P[mt][2 * np + 1][3] * inv1);
            aP[mt][np][0] = *reinterpret_cast<uint32_t*>(&p0);
            aP[mt][np][1] = *reinterpret_cast<uint32_t*>(&p1);
            aP[mt][np][2] = *reinterpret_cast<uint32_t*>(&p2);
            aP[mt][np][3] = *reinterpret_cast<uint32_t*>(&p3);
        }
    }

    float O[MT][8][4];
    #pragma unroll
    for (int mt = 0; mt < MT; mt++)
        #pragma unroll
        for (int nt = 0; nt < 8; nt++)
            #pragma unroll
            for (int q = 0; q < 4; q++) O[mt][nt][q] = 0.f;

    #pragma unroll
    for (int kt = 0; kt < NP; kt++) {
        #pragma unroll
        for (int vp = 0; vp < 4; vp++) {
            uint32_t bV[4];
            int krow = kt * 16 + (lane & 7) + (((lane >> 3) & 1) << 3);
            int c = cb + vp * 2 + (lane >> 4);
            ldsm_x4_t(smV + (uint32_t)krow * 512 + (uint32_t)((c ^ (krow & 7)) << 4), bV);
            #pragma unroll
            for (int mt = 0; mt < MT; mt++) {
                mma16816(O[mt][vp * 2], aP[mt][kt], bV[0], bV[1]);
                mma16816(O[mt][vp * 2 + 1], aP[mt][kt], bV[2], bV[3]);
            }
        }
    }

    const int ocol0 = axis * 512 + (hp * 4 + wp) * 64;
    #pragma unroll
    for (int mt = 0; mt < MT; mt++) {
        int r = mt * 16 + (lane >> 2);
        size_t rowOffA = (size_t)(n0 + r * st) * 1536 + ocol0;
        size_t rowOffB = (size_t)(n0 + (r + 8) * st) * 1536 + ocol0;
        #pragma unroll
        for (int nt = 0; nt < 8; nt++) {
            int col = nt * 8 + (lane & 3) * 2;
            *reinterpret_cast<__half2*>(g_O + rowOffA + col) =
                __floats2half2_rn(O[mt][nt][0], O[mt][nt][1]);
            *reinterpret_cast<__half2*>(g_O + rowOffB + col) =
                __floats2half2_rn(O[mt][nt][2], O[mt][nt][3]);
        }
    }
}

__global__ void __launch_bounds__(128)
attn_all_k() {
    extern __shared__ __align__(128) char sm[];
    const uint32_t base = smem_u32(sm);
    const int tid = threadIdx.x;
    const int id = blockIdx.x;

    if (id < 8192) {                         // axes w (0..4095) and h (4096..8191)
        int axis = id >> 12;
        int r = id & 4095;
        int b = r >> 10;
        int g = r & 1023;
        int hp = g & 1, grp = g >> 1;
        int n0, st;
        if (axis == 0) { n0 = b * Ss + grp * 32;                        st = 1;  }
        else           { n0 = b * Ss + (grp >> 5) * 1024 + (grp & 31);  st = 32; }
        attn_body<32>(axis, hp, n0, st, base, tid);
    } else {                                 // axis t (8192..16383)
        int r = id - 8192;
        int b = r >> 11;
        int g = r & 2047;
        int hp = g & 1, grp = g >> 1;
        attn_body<16>(2, hp, b * Ss + grp, 1024, base, tid);
    }
}

// ---------------------------------------------------------------------------
// Launch: pure serial on the default stream. 5 kernels.
// ---------------------------------------------------------------------------
extern "C" void kernel_launch(void* const* d_in, const int* in_sizes, int n_in,
                              void* d_out, int out_size) {
    (void)in_sizes; (void)n_in; (void)out_size;
    const float* x = (const float*)d_in[0];
    const float* wq[3] = {(const float*)d_in[1],  (const float*)d_in[6],  (const float*)d_in[11]};
    const float* wk[3] = {(const float*)d_in[2],  (const float*)d_in[7],  (const float*)d_in[12]};
    const float* wv[3] = {(const float*)d_in[3],  (const float*)d_in[8],  (const float*)d_in[13]};
    const float* wo[3] = {(const float*)d_in[4],  (const float*)d_in[9],  (const float*)d_in[14]};
    const float* bo[3] = {(const float*)d_in[5],  (const float*)d_in[10], (const float*)d_in[15]};
    float* out = (float*)d_out;

    void *pX, *pQKV, *pO, *pWqkv, *pWo, *pBias;
    cudaGetSymbolAddress(&pX, g_X);
    cudaGetSymbolAddress(&pQKV, g_QKV);
    cudaGetSymbolAddress(&pO, g_O);
    cudaGetSymbolAddress(&pWqkv, g_Wqkv);
    cudaGetSymbolAddress(&pWo, g_Wo);
    cudaGetSymbolAddress(&pBias, g_bias);

    cudaFuncSetAttribute(gemm_qkv_k,
                         cudaFuncAttributeMaxDynamicSharedMemorySize, QK_DSMEM);
    cudaFuncSetAttribute(gemm_out_k,
                         cudaFuncAttributeMaxDynamicSharedMemorySize, GEMM_DSMEM);
    cudaFuncSetAttribute(attn_all_k,
                         cudaFuncAttributeMaxDynamicSharedMemorySize, 3 * 32 * 512);

    // 0: all weight prep (merged)
    prep_all_k<<<(3 * 786432 + 3 * 262144 + 255) / 256, 256>>>(
        wq[0], wk[0], wv[0], wq[1], wk[1], wv[1], wq[2], wk[2], wv[2],
        wo[0], wo[1], wo[2], bo[0], bo[1], bo[2]);
    // 1: input transpose
    transpose_in_k<<<dim3(Ss / 32, Cc / 64, Bb), dim3(32, 8)>>>(x);

    // 2: fused QKV projection (champion BK=64 config)
    gemm_qkv_k<<<dim3(4608 / 96, Nn / 128), 128, QK_DSMEM>>>(
        (const __half*)pX, (const __half*)pWqkv, (__half*)pQKV);

    // 3: all axial attention in one launch
    attn_all_k<<<16384, 128, 3 * 32 * 512>>>();

    // 4: output projection, all batches
    gemm_out_k<<<dim3(4, Ss / 128, Bb), 128, GEMM_DSMEM>>>(
        (const __half*)pWo, (const __half*)pO, out, (const float*)pBias);
}